// round 1
// baseline (speedup 1.0000x reference)
#include <cuda_runtime.h>

// Shapes (fixed by the problem)
//  B=4, N_FRAMES=32 -> BN=128 rows; C=256, S=16 -> HW=256, CHW=65536; D=512.
// Key simplification: softmax over a size-1 axis == 1, so attn = (v_next@Wv.T+bv)@Wo.T+bo.

#define EPS_ 1e-5f

// ---------------- scratch (single __device__ array, ~112 MB) ----------------
// ws   : 32*128*512  = 2,097,152
// tp   : 128*512     =    65,536
// vv   : 65,536   attn: 65,536   enh: 65,536
// fa   : 128*65536   = 8,388,608
// b1   : 8,388,608   b2: 8,388,608
// gap  : 32,768      hid: 32,768
// kern : 128*2304    = 294,912
// mu   : 128         rs : 128
__device__ float g_scratch[27885824];

__device__ __forceinline__ float warp_sum(float v) {
#pragma unroll
    for (int o = 16; o; o >>= 1) v += __shfl_down_sync(0xffffffffu, v, o);
    return v;
}

// ---------------------------------------------------------------------------
// GEMM1 split-K: ws[sp][m][n] = sum_{k in sp-chunk(2048)} feat[m,k] * Wp[n,k]
// grid (8 ntiles, 2 mtiles, 32 splits), 256 threads, BM=BN=64, BK=16, 4x4/thread
// ---------------------------------------------------------------------------
__global__ __launch_bounds__(256) void gemm1_split_kernel(
    const float* __restrict__ A, const float* __restrict__ B, float* __restrict__ ws)
{
    const int n0 = blockIdx.x * 64, m0 = blockIdx.y * 64, sp = blockIdx.z;
    const int tid = threadIdx.x;
    const int lr = tid >> 2, lc = (tid & 3) << 2;
    const int trow = tid >> 4, tcol = tid & 15;
    __shared__ float As[16][64];
    __shared__ float Bs[16][64];
    float acc[16];
#pragma unroll
    for (int i = 0; i < 16; i++) acc[i] = 0.f;
    const float* Ap = A + (size_t)(m0 + lr) * 65536 + sp * 2048 + lc;
    const float* Bp = B + (size_t)(n0 + lr) * 65536 + sp * 2048 + lc;
    for (int kt = 0; kt < 2048; kt += 16) {
        float4 av = *(const float4*)(Ap + kt);
        float4 bv = *(const float4*)(Bp + kt);
        As[lc + 0][lr] = av.x; As[lc + 1][lr] = av.y; As[lc + 2][lr] = av.z; As[lc + 3][lr] = av.w;
        Bs[lc + 0][lr] = bv.x; Bs[lc + 1][lr] = bv.y; Bs[lc + 2][lr] = bv.z; Bs[lc + 3][lr] = bv.w;
        __syncthreads();
#pragma unroll
        for (int kk = 0; kk < 16; kk++) {
            float4 a = *(const float4*)&As[kk][trow << 2];
            float4 b = *(const float4*)&Bs[kk][tcol << 2];
            float ar[4] = {a.x, a.y, a.z, a.w}, br[4] = {b.x, b.y, b.z, b.w};
#pragma unroll
            for (int i = 0; i < 4; i++)
#pragma unroll
                for (int j = 0; j < 4; j++) acc[i * 4 + j] += ar[i] * br[j];
        }
        __syncthreads();
    }
    float* W = ws + (size_t)sp * 65536;
#pragma unroll
    for (int i = 0; i < 4; i++)
#pragma unroll
        for (int j = 0; j < 4; j++)
            W[(m0 + (trow << 2) + i) * 512 + n0 + (tcol << 2) + j] = acc[i * 4 + j];
}

// tp[m][n] = bp[n] + sum_sp ws[sp][m][n]   (deterministic fixed-order reduce)
__global__ __launch_bounds__(256) void g1reduce_kernel(
    const float* __restrict__ ws, const float* __restrict__ bp, float* __restrict__ tp)
{
    int idx = blockIdx.x * 256 + threadIdx.x;  // 65536 total
    float s = bp[idx & 511];
#pragma unroll 8
    for (int sp = 0; sp < 32; sp++) s += ws[sp * 65536 + idx];
    tp[idx] = s;
}

// ---------------------------------------------------------------------------
// Generic C[m,n] = act( sum_k A[m,k]*B[n,k] + bias[n] ), both K-contiguous.
// SHIFT=1 remaps A rows within frame-blocks of 32: i -> min(i+1,31) (v_next).
// grid ((N/64), (M/64)), 256 threads, BK=16, 4x4 per thread.
// ---------------------------------------------------------------------------
template <int SHIFT, int RELU>
__global__ __launch_bounds__(256) void gemm_nt_kernel(
    const float* __restrict__ A, const float* __restrict__ B,
    const float* __restrict__ bias, float* __restrict__ C, int N, int K)
{
    const int n0 = blockIdx.x * 64, m0 = blockIdx.y * 64;
    const int tid = threadIdx.x;
    const int lr = tid >> 2, lc = (tid & 3) << 2;
    const int trow = tid >> 4, tcol = tid & 15;
    __shared__ float As[16][64];
    __shared__ float Bs[16][64];
    float acc[16];
#pragma unroll
    for (int i = 0; i < 16; i++) acc[i] = 0.f;
    int am = m0 + lr;
    if (SHIFT) {
        int bb = am >> 5, ii = (am & 31) + 1;
        if (ii > 31) ii = 31;
        am = (bb << 5) + ii;
    }
    const float* Ap = A + (size_t)am * K + lc;
    const float* Bp = B + (size_t)(n0 + lr) * K + lc;
    for (int kt = 0; kt < K; kt += 16) {
        float4 av = *(const float4*)(Ap + kt);
        float4 bv = *(const float4*)(Bp + kt);
        As[lc + 0][lr] = av.x; As[lc + 1][lr] = av.y; As[lc + 2][lr] = av.z; As[lc + 3][lr] = av.w;
        Bs[lc + 0][lr] = bv.x; Bs[lc + 1][lr] = bv.y; Bs[lc + 2][lr] = bv.z; Bs[lc + 3][lr] = bv.w;
        __syncthreads();
#pragma unroll
        for (int kk = 0; kk < 16; kk++) {
            float4 a = *(const float4*)&As[kk][trow << 2];
            float4 b = *(const float4*)&Bs[kk][tcol << 2];
            float ar[4] = {a.x, a.y, a.z, a.w}, br[4] = {b.x, b.y, b.z, b.w};
#pragma unroll
            for (int i = 0; i < 4; i++)
#pragma unroll
                for (int j = 0; j < 4; j++) acc[i * 4 + j] += ar[i] * br[j];
        }
        __syncthreads();
    }
#pragma unroll
    for (int j = 0; j < 4; j++) {
        float bj = bias[n0 + (tcol << 2) + j];
#pragma unroll
        for (int i = 0; i < 4; i++) {
            float v = acc[i * 4 + j] + bj;
            if (RELU) v = fmaxf(v, 0.f);
            C[(size_t)(m0 + (trow << 2) + i) * N + n0 + (tcol << 2) + j] = v;
        }
    }
}

// ---------------------------------------------------------------------------
// LayerNorm over D=512: enh = LN(attn + tp)*g + b. 128 blocks x 512 threads.
// ---------------------------------------------------------------------------
__global__ __launch_bounds__(512) void ln1_kernel(
    const float* __restrict__ attn, const float* __restrict__ tp,
    const float* __restrict__ g, const float* __restrict__ b, float* __restrict__ enh)
{
    int m = blockIdx.x, t = threadIdx.x;
    float x = attn[m * 512 + t] + tp[m * 512 + t];
    __shared__ float sS[16], sQ[16];
    __shared__ float mu_s, rs_s;
    float s = warp_sum(x), q = warp_sum(x * x);
    int wid = t >> 5, lane = t & 31;
    if (lane == 0) { sS[wid] = s; sQ[wid] = q; }
    __syncthreads();
    if (t == 0) {
        float S = 0, Q = 0;
        for (int i = 0; i < 16; i++) { S += sS[i]; Q += sQ[i]; }
        float mu = S * (1.f / 512.f);
        float var = Q * (1.f / 512.f) - mu * mu;
        mu_s = mu; rs_s = rsqrtf(var + EPS_);
    }
    __syncthreads();
    enh[m * 512 + t] = (x - mu_s) * rs_s * g[t] + b[t];
}

// gap[m][c] = mean over 256 pixels of fa[m][c][:]. 128 blocks x 256 threads.
__global__ __launch_bounds__(256) void gap_kernel(
    const float* __restrict__ fa, float* __restrict__ gap)
{
    int m = blockIdx.x, t = threadIdx.x;
    int wid = t >> 5, lane = t & 31;
    for (int it = 0; it < 32; it++) {
        int c = wid * 32 + it;
        const float* p = fa + (size_t)m * 65536 + c * 256 + lane * 8;
        float4 a = *(const float4*)p;
        float4 b = *(const float4*)(p + 4);
        float s = a.x + a.y + a.z + a.w + b.x + b.y + b.z + b.w;
        s = warp_sum(s);
        if (lane == 0) gap[m * 256 + c] = s * (1.f / 256.f);
    }
}

// Depthwise 3x3 with per-(sample,channel) kernels. grid (c=256, m=128), 256 thr.
__global__ __launch_bounds__(256) void dw_kernel(
    const float* __restrict__ fa, const float* __restrict__ kern, float* __restrict__ out)
{
    int c = blockIdx.x, m = blockIdx.y, t = threadIdx.x;
    __shared__ float tile[18][18];
    __shared__ float k9[9];
    for (int i = t; i < 324; i += 256) ((float*)tile)[i] = 0.f;
    __syncthreads();
    int h = t >> 4, w = t & 15;
    size_t base = (size_t)m * 65536 + c * 256;
    tile[h + 1][w + 1] = fa[base + t];
    if (t < 9) k9[t] = kern[m * 2304 + c * 9 + t];
    __syncthreads();
    float s = 0.f;
#pragma unroll
    for (int di = 0; di < 3; di++)
#pragma unroll
        for (int dj = 0; dj < 3; dj++)
            s += k9[di * 3 + dj] * tile[h + di][w + dj];
    out[base + t] = s;
}

// ---------------------------------------------------------------------------
// Batched 1x1 conv: O[n][d][p] = act( sum_c W[d][c]*X[n][c][p] + bias[d] ) (+res)
// grid (8 dtiles of 32, n=128), 256 threads; thread tile 4d x 8p; BK=16.
// ---------------------------------------------------------------------------
template <int RELU, int RES>
__global__ __launch_bounds__(256) void conv1x1_kernel(
    const float* __restrict__ X, const float* __restrict__ W,
    const float* __restrict__ bias, const float* __restrict__ res, float* __restrict__ O)
{
    const int d0 = blockIdx.x * 32;
    const int n = blockIdx.y;
    const int t = threadIdx.x;
    const int trow = t >> 5, tcol = t & 31;
    __shared__ float Ws[16][32];
    __shared__ float Xs[16][256];
    float acc[32];
#pragma unroll
    for (int i = 0; i < 32; i++) acc[i] = 0.f;
    const float* Xn = X + (size_t)n * 65536;
    for (int c0 = 0; c0 < 256; c0 += 16) {
        if (t < 128) {
            int r = t >> 2, cc = (t & 3) << 2;
            float4 wv = *(const float4*)&W[(d0 + r) * 256 + c0 + cc];
            Ws[cc + 0][r] = wv.x; Ws[cc + 1][r] = wv.y; Ws[cc + 2][r] = wv.z; Ws[cc + 3][r] = wv.w;
        }
#pragma unroll
        for (int j = 0; j < 4; j++) {
            int q = t + (j << 8);
            int c = q >> 6, p4 = q & 63;
            *(float4*)&Xs[c][p4 << 2] = *(const float4*)&Xn[(c0 + c) * 256 + (p4 << 2)];
        }
        __syncthreads();
#pragma unroll
        for (int k = 0; k < 16; k++) {
            float wv[4];
#pragma unroll
            for (int i = 0; i < 4; i++) wv[i] = Ws[k][(trow << 2) + i];
            float4 x0 = *(const float4*)&Xs[k][tcol << 3];
            float4 x1 = *(const float4*)&Xs[k][(tcol << 3) + 4];
            float xv[8] = {x0.x, x0.y, x0.z, x0.w, x1.x, x1.y, x1.z, x1.w};
#pragma unroll
            for (int i = 0; i < 4; i++)
#pragma unroll
                for (int j = 0; j < 8; j++) acc[i * 8 + j] += wv[i] * xv[j];
        }
        __syncthreads();
    }
#pragma unroll
    for (int i = 0; i < 4; i++) {
        int d = d0 + (trow << 2) + i;
        float bd = bias[d];
        size_t base = (size_t)n * 65536 + d * 256 + (tcol << 3);
#pragma unroll
        for (int j = 0; j < 8; j++) {
            float v = acc[i * 8 + j] + bd;
            if (RELU) v = fmaxf(v, 0.f);
            if (RES) v += res[base + j];
            O[base + j] = v;
        }
    }
}

// GroupNorm: 32 groups of (8 ch x 256 px) = 2048 elems. grid (g=32, m=128), 256 thr.
__global__ __launch_bounds__(256) void gn_kernel(
    const float* __restrict__ X, const float* __restrict__ gg,
    const float* __restrict__ gb, float* __restrict__ O)
{
    int g = blockIdx.x, m = blockIdx.y, t = threadIdx.x;
    size_t base = (size_t)m * 65536 + g * 2048;
    float4 v0 = *(const float4*)&X[base + t * 8];
    float4 v1 = *(const float4*)&X[base + t * 8 + 4];
    float s = v0.x + v0.y + v0.z + v0.w + v1.x + v1.y + v1.z + v1.w;
    float q = v0.x * v0.x + v0.y * v0.y + v0.z * v0.z + v0.w * v0.w +
              v1.x * v1.x + v1.y * v1.y + v1.z * v1.z + v1.w * v1.w;
    __shared__ float sS[8], sQ[8];
    __shared__ float mu_s, rs_s;
    s = warp_sum(s); q = warp_sum(q);
    int wid = t >> 5, lane = t & 31;
    if (lane == 0) { sS[wid] = s; sQ[wid] = q; }
    __syncthreads();
    if (t == 0) {
        float S = 0, Q = 0;
        for (int i = 0; i < 8; i++) { S += sS[i]; Q += sQ[i]; }
        float mu = S * (1.f / 2048.f);
        float var = Q * (1.f / 2048.f) - mu * mu;
        mu_s = mu; rs_s = rsqrtf(var + EPS_);
    }
    __syncthreads();
    float vals[8] = {v0.x, v0.y, v0.z, v0.w, v1.x, v1.y, v1.z, v1.w};
#pragma unroll
    for (int j = 0; j < 8; j++) {
        int local = t * 8 + j;
        int c = g * 8 + (local >> 8);
        O[base + local] = (vals[j] - mu_s) * rs_s * gg[c] + gb[c];
    }
}

// Per-sample stats over 65536 elems. 128 blocks x 256 threads.
__global__ __launch_bounds__(256) void zstats_kernel(
    const float* __restrict__ z, float* __restrict__ mu_out, float* __restrict__ rs_out)
{
    int m = blockIdx.x, t = threadIdx.x;
    const float* row = z + (size_t)m * 65536;
    float s = 0.f, q = 0.f;
    for (int i = t * 4; i < 65536; i += 1024) {
        float4 v = *(const float4*)&row[i];
        s += v.x + v.y + v.z + v.w;
        q += v.x * v.x + v.y * v.y + v.z * v.z + v.w * v.w;
    }
    __shared__ float sS[8], sQ[8];
    s = warp_sum(s); q = warp_sum(q);
    int wid = t >> 5, lane = t & 31;
    if (lane == 0) { sS[wid] = s; sQ[wid] = q; }
    __syncthreads();
    if (t == 0) {
        float S = 0, Q = 0;
        for (int i = 0; i < 8; i++) { S += sS[i]; Q += sQ[i]; }
        float mu = S * (1.f / 65536.f);
        float var = Q * (1.f / 65536.f) - mu * mu;
        mu_out[m] = mu;
        rs_out[m] = rsqrtf(var + EPS_);
    }
}

// out[m][j] = (z - mu[m]) * rs[m] * dn_g[j] + dn_b[j]. 8192 blocks x 256 thr x float4.
__global__ __launch_bounds__(256) void final_kernel(
    const float* __restrict__ z, const float* __restrict__ mu, const float* __restrict__ rs,
    const float* __restrict__ dg, const float* __restrict__ db, float* __restrict__ out)
{
    int i4 = blockIdx.x * 256 + threadIdx.x;
    int idx = i4 * 4;
    int m = idx >> 16, j = idx & 65535;
    float4 zv = *(const float4*)&z[idx];
    float4 gv = *(const float4*)&dg[j];
    float4 bv = *(const float4*)&db[j];
    float mm = mu[m], rr = rs[m];
    float4 o;
    o.x = (zv.x - mm) * rr * gv.x + bv.x;
    o.y = (zv.y - mm) * rr * gv.y + bv.y;
    o.z = (zv.z - mm) * rr * gv.z + bv.z;
    o.w = (zv.w - mm) * rr * gv.w + bv.w;
    *(float4*)&out[idx] = o;
}

// ---------------------------------------------------------------------------
extern "C" void kernel_launch(void* const* d_in, const int* in_sizes, int n_in,
                              void* d_out, int out_size)
{
    const float* feat = (const float*)d_in[0];
    const float* Wp   = (const float*)d_in[1];
    const float* bp   = (const float*)d_in[2];
    const float* Wu   = (const float*)d_in[3];
    const float* bu   = (const float*)d_in[4];
    // d_in[5..8] = Wq,bq,Wk,bk -> dead (softmax over size-1 axis == 1)
    const float* Wv   = (const float*)d_in[9];
    const float* bv   = (const float*)d_in[10];
    const float* Wo   = (const float*)d_in[11];
    const float* bo   = (const float*)d_in[12];
    const float* ln1g = (const float*)d_in[13];
    const float* ln1b = (const float*)d_in[14];
    const float* Wk1  = (const float*)d_in[15];
    const float* bk1  = (const float*)d_in[16];
    const float* Wk2  = (const float*)d_in[17];
    const float* bk2  = (const float*)d_in[18];
    const float* Wpc  = (const float*)d_in[19];
    const float* bpc  = (const float*)d_in[20];
    const float* gng  = (const float*)d_in[21];
    const float* gnb  = (const float*)d_in[22];
    const float* Wf1  = (const float*)d_in[23];
    const float* bf1  = (const float*)d_in[24];
    const float* Wf2  = (const float*)d_in[25];
    const float* bf2  = (const float*)d_in[26];
    const float* dng  = (const float*)d_in[27];
    const float* dnb  = (const float*)d_in[28];
    float* out = (float*)d_out;

    void* sp_ = nullptr;
    cudaGetSymbolAddress(&sp_, g_scratch);
    float* s = (float*)sp_;
    float* ws   = s;                  // 2,097,152
    float* tp   = ws + 2097152;       // 65,536
    float* vv   = tp + 65536;
    float* attn = vv + 65536;
    float* enh  = attn + 65536;
    float* fa   = enh + 65536;        // 8,388,608
    float* b1   = fa + 8388608;
    float* b2   = b1 + 8388608;
    float* gapb = b2 + 8388608;       // 32,768
    float* hid  = gapb + 32768;
    float* kern = hid + 32768;        // 294,912
    float* muv  = kern + 294912;      // 128
    float* rsv  = muv + 128;

    // 1) tp = tokens @ Wp.T + bp   (split-K, deterministic reduce)
    gemm1_split_kernel<<<dim3(8, 2, 32), 256>>>(feat, Wp, ws);
    g1reduce_kernel<<<256, 256>>>(ws, bp, tp);
    // 2) vv = v_next @ Wv.T + bv  (SHIFT row-map), attn = vv @ Wo.T + bo
    gemm_nt_kernel<1, 0><<<dim3(8, 2), 256>>>(tp, Wv, bv, vv, 512, 512);
    gemm_nt_kernel<0, 0><<<dim3(8, 2), 256>>>(vv, Wo, bo, attn, 512, 512);
    // 3) enh = LN(attn + tp)
    ln1_kernel<<<128, 512>>>(attn, tp, ln1g, ln1b, enh);
    // 4) feat_attn = enh @ Wu.T + bu
    gemm_nt_kernel<0, 0><<<dim3(1024, 2), 256>>>(enh, Wu, bu, fa, 65536, 512);
    // 5) gap -> hid -> kern
    gap_kernel<<<128, 256>>>(fa, gapb);
    gemm_nt_kernel<0, 1><<<dim3(4, 2), 256>>>(gapb, Wk1, bk1, hid, 256, 256);
    gemm_nt_kernel<0, 0><<<dim3(36, 2), 256>>>(hid, Wk2, bk2, kern, 2304, 256);
    // 6) depthwise 3x3 (per-sample per-channel kernels)
    dw_kernel<<<dim3(256, 128), 256>>>(fa, kern, b1);
    // 7) pointwise Wpc + bpc, then GroupNorm
    conv1x1_kernel<0, 0><<<dim3(8, 128), 256>>>(b1, Wpc, bpc, nullptr, b2);
    gn_kernel<<<dim3(32, 128), 256>>>(b2, gng, gnb, b1);
    // 8) y = relu(conv Wf1), y = conv Wf2 + feat_attn (residual)
    conv1x1_kernel<1, 0><<<dim3(8, 128), 256>>>(b1, Wf1, bf1, nullptr, b2);
    conv1x1_kernel<0, 1><<<dim3(8, 128), 256>>>(b2, Wf2, bf2, fa, b1);
    // 9) per-sample LayerNorm over 65536 + affine dn_g/dn_b
    zstats_kernel<<<128, 256>>>(b1, muv, rsv);
    final_kernel<<<8192, 256>>>(b1, muv, rsv, dng, dnb, out);
}

// round 3
// speedup vs baseline: 2.0992x; 2.0992x over previous
#include <cuda_runtime.h>
#include <cuda_bf16.h>
#include <cstdint>

#define EPS_ 1e-5f

// ---------------- scratch (single __device__ array) ----------------
__device__ float g_scratch[27885824];

__device__ __forceinline__ float warp_sum(float v) {
#pragma unroll
    for (int o = 16; o; o >>= 1) v += __shfl_down_sync(0xffffffffu, v, o);
    return v;
}

// split fp32 -> (hi bf16, lo bf16) pairs packed as bf16x2 words
__device__ __forceinline__ void cvt_split(float a, float b, uint32_t& hi, uint32_t& lo) {
    __nv_bfloat162 h = __floats2bfloat162_rn(a, b);
    float2 hf = __bfloat1622float2(h);
    __nv_bfloat162 l = __floats2bfloat162_rn(a - hf.x, b - hf.y);
    hi = *reinterpret_cast<uint32_t*>(&h);
    lo = *reinterpret_cast<uint32_t*>(&l);
}

__device__ __forceinline__ void mma16816(float* c, const uint32_t* a, const uint32_t* b) {
    asm volatile(
        "mma.sync.aligned.m16n8k16.row.col.f32.bf16.bf16.f32 "
        "{%0,%1,%2,%3}, {%4,%5,%6,%7}, {%8,%9}, {%0,%1,%2,%3};"
        : "+f"(c[0]), "+f"(c[1]), "+f"(c[2]), "+f"(c[3])
        : "r"(a[0]), "r"(a[1]), "r"(a[2]), "r"(a[3]), "r"(b[0]), "r"(b[1]));
}

// ===========================================================================
// mma.sync GEMM: C[m,n] = act( sum_k A[m,k]*B[n,k] (+bias) (+res) )
// Block: 256 thr (8 warps), tile M=128 (blockIdx.y), N=64 (blockIdx.x),
// split-K = blockIdx.z (chunk length kLen). K-chunk 32 (bf16x3 split MMAs).
// Warp w: wm=(w>>1)*32, wn=(w&1)*32, 32x32 per warp = 2x4 m16n8k16 frags.
// SHIFT: remap A rows within frame-blocks of 32 (v_next).
// BCONV=1: B = X[n,c,p] gather (1x1 conv); column block = 64 px of one sample.
// EPI: 0=partial (split-K, no bias), 1=bias, 2=bias+relu, 3=bias+residual.
// Smem tiles padded to stride 40 bf16 (20 words): conflict-free frag loads.
// ===========================================================================
#define SA 20  // row stride in 32-bit words (40 bf16)
template <int SHIFT, int BCONV, int EPI>
__global__ __launch_bounds__(256) void mg_kernel(
    const float* __restrict__ A, const float* __restrict__ Bm,
    const float* __restrict__ bias, const float* __restrict__ res,
    float* __restrict__ C, int K, int kLen, int Ntot, int Astride)
{
    __shared__ uint32_t AsH[128 * SA], AsL[128 * SA], BsH[64 * SA], BsL[64 * SA];
    const int t = threadIdx.x, w = t >> 5, lid = t & 31;
    const int wm = (w >> 1) * 32, wn = (w & 1) * 32;
    const int t4 = lid & 3, grp = lid >> 2;
    const int n0 = blockIdx.x * 64;
    const int m0 = blockIdx.y * 128;
    const int sp = blockIdx.z;
    const int k0base = sp * kLen;
    const int nn = n0 >> 8, p0 = n0 & 255;  // BCONV decode

    float acc[2][4][4];
#pragma unroll
    for (int i = 0; i < 2; i++)
#pragma unroll
        for (int j = 0; j < 4; j++)
#pragma unroll
            for (int q = 0; q < 4; q++) acc[i][j][q] = 0.f;

    // A-load mapping: row = t>>1, 16 consecutive cols at (t&1)*16
    int am = m0 + (t >> 1);
    if (SHIFT) { int bb = am >> 5, ii = (am & 31) + 1; if (ii > 31) ii = 31; am = (bb << 5) + ii; }
    const float* Aptr = A + (size_t)am * Astride + k0base + (t & 1) * 16;
    const int awb = (t >> 1) * SA + (t & 1) * 8;

    const int nchunks = kLen >> 5;
    for (int ch = 0; ch < nchunks; ch++) {
        const int kc = ch << 5;
        __syncthreads();
        // ---- A tile 128x32 ----
        {
            const float* p = Aptr + kc;
#pragma unroll
            for (int i = 0; i < 16; i += 4) {
                float4 v = *(const float4*)(p + i);
                uint32_t h0, l0, h1, l1;
                cvt_split(v.x, v.y, h0, l0);
                cvt_split(v.z, v.w, h1, l1);
                AsH[awb + i / 2] = h0; AsH[awb + i / 2 + 1] = h1;
                AsL[awb + i / 2] = l0; AsL[awb + i / 2 + 1] = l1;
            }
        }
        // ---- B tile 64x32 ----
        if (!BCONV) {
            const int j = t >> 2, cb = (t & 3) * 8;
            const float* p = Bm + (size_t)(n0 + j) * K + k0base + kc + cb;
            const int wb = j * SA + cb / 2;
#pragma unroll
            for (int i = 0; i < 8; i += 4) {
                float4 v = *(const float4*)(p + i);
                uint32_t h0, l0, h1, l1;
                cvt_split(v.x, v.y, h0, l0);
                cvt_split(v.z, v.w, h1, l1);
                BsH[wb + i / 2] = h0; BsH[wb + i / 2 + 1] = h1;
                BsL[wb + i / 2] = l0; BsL[wb + i / 2 + 1] = l1;
            }
        } else {
            const int j = t & 63, cg = t >> 6;
            const float* Xb = Bm + (size_t)nn * 65536 + (size_t)(kc + cg * 8) * 256 + p0 + j;
            const int wb = j * SA + cg * 4;
#pragma unroll
            for (int i = 0; i < 8; i += 2) {
                float a = Xb[i * 256], b = Xb[(i + 1) * 256];
                uint32_t h, l;
                cvt_split(a, b, h, l);
                BsH[wb + i / 2] = h;
                BsL[wb + i / 2] = l;
            }
        }
        __syncthreads();
        // ---- compute: 2 k16 steps, 3 split passes each ----
#pragma unroll
        for (int ks = 0; ks < 2; ks++) {
            uint32_t ah[2][4], al[2][4], bh[4][2], bl[4][2];
#pragma unroll
            for (int mi = 0; mi < 2; mi++) {
                const int rb = (wm + mi * 16 + grp) * SA + ks * 8 + t4;
                ah[mi][0] = AsH[rb];       ah[mi][1] = AsH[rb + 8 * SA];
                ah[mi][2] = AsH[rb + 4];   ah[mi][3] = AsH[rb + 8 * SA + 4];
            }
#pragma unroll
            for (int ni = 0; ni < 4; ni++) {
                const int nb = (wn + ni * 8 + grp) * SA + ks * 8 + t4;
                bh[ni][0] = BsH[nb]; bh[ni][1] = BsH[nb + 4];
            }
#pragma unroll
            for (int mi = 0; mi < 2; mi++)
#pragma unroll
                for (int ni = 0; ni < 4; ni++) mma16816(acc[mi][ni], ah[mi], bh[ni]);
#pragma unroll
            for (int ni = 0; ni < 4; ni++) {
                const int nb = (wn + ni * 8 + grp) * SA + ks * 8 + t4;
                bl[ni][0] = BsL[nb]; bl[ni][1] = BsL[nb + 4];
            }
#pragma unroll
            for (int mi = 0; mi < 2; mi++)
#pragma unroll
                for (int ni = 0; ni < 4; ni++) mma16816(acc[mi][ni], ah[mi], bl[ni]);
#pragma unroll
            for (int mi = 0; mi < 2; mi++) {
                const int rb = (wm + mi * 16 + grp) * SA + ks * 8 + t4;
                al[mi][0] = AsL[rb];       al[mi][1] = AsL[rb + 8 * SA];
                al[mi][2] = AsL[rb + 4];   al[mi][3] = AsL[rb + 8 * SA + 4];
            }
#pragma unroll
            for (int mi = 0; mi < 2; mi++)
#pragma unroll
                for (int ni = 0; ni < 4; ni++) mma16816(acc[mi][ni], al[mi], bh[ni]);
        }
    }

    // ---- epilogue ----
#pragma unroll
    for (int mi = 0; mi < 2; mi++) {
        const int r0 = m0 + wm + mi * 16 + grp;
        const int r1 = r0 + 8;
        if (EPI == 0) {
            float* C0 = C + ((size_t)sp * 128 + r0) * Ntot + n0;
            float* C1 = C + ((size_t)sp * 128 + r1) * Ntot + n0;
#pragma unroll
            for (int ni = 0; ni < 4; ni++) {
                const int cw = wn + ni * 8 + 2 * t4;
                *(float2*)(C0 + cw) = make_float2(acc[mi][ni][0], acc[mi][ni][1]);
                *(float2*)(C1 + cw) = make_float2(acc[mi][ni][2], acc[mi][ni][3]);
            }
        } else if (!BCONV) {
            float* C0 = C + (size_t)r0 * Ntot;
            float* C1 = C + (size_t)r1 * Ntot;
#pragma unroll
            for (int ni = 0; ni < 4; ni++) {
                const int col = n0 + wn + ni * 8 + 2 * t4;
                float b0 = bias[col], b1 = bias[col + 1];
                float2 o0 = make_float2(acc[mi][ni][0] + b0, acc[mi][ni][1] + b1);
                float2 o1 = make_float2(acc[mi][ni][2] + b0, acc[mi][ni][3] + b1);
                if (EPI == 2) {
                    o0.x = fmaxf(o0.x, 0.f); o0.y = fmaxf(o0.y, 0.f);
                    o1.x = fmaxf(o1.x, 0.f); o1.y = fmaxf(o1.y, 0.f);
                }
                *(float2*)(C0 + col) = o0;
                *(float2*)(C1 + col) = o1;
            }
        } else {
            const float bm0 = bias[r0], bm1 = bias[r1];
            float* P0 = C + (size_t)nn * 65536 + (size_t)r0 * 256 + p0;
            float* P1 = C + (size_t)nn * 65536 + (size_t)r1 * 256 + p0;
            const float* R0 = (EPI == 3) ? res + (size_t)nn * 65536 + (size_t)r0 * 256 + p0 : nullptr;
            const float* R1 = (EPI == 3) ? res + (size_t)nn * 65536 + (size_t)r1 * 256 + p0 : nullptr;
#pragma unroll
            for (int ni = 0; ni < 4; ni++) {
                const int cw = wn + ni * 8 + 2 * t4;
                float2 o0 = make_float2(acc[mi][ni][0] + bm0, acc[mi][ni][1] + bm0);
                float2 o1 = make_float2(acc[mi][ni][2] + bm1, acc[mi][ni][3] + bm1);
                if (EPI == 2) {
                    o0.x = fmaxf(o0.x, 0.f); o0.y = fmaxf(o0.y, 0.f);
                    o1.x = fmaxf(o1.x, 0.f); o1.y = fmaxf(o1.y, 0.f);
                }
                if (EPI == 3) {
                    float2 q0 = *(const float2*)(R0 + cw);
                    float2 q1 = *(const float2*)(R1 + cw);
                    o0.x += q0.x; o0.y += q0.y; o1.x += q1.x; o1.y += q1.y;
                }
                *(float2*)(P0 + cw) = o0;
                *(float2*)(P1 + cw) = o1;
            }
        }
    }
}

// ===================== SIMT kernels (mem-bound) =====================
__global__ __launch_bounds__(256) void g1reduce_kernel(
    const float* __restrict__ ws, const float* __restrict__ bp, float* __restrict__ tp)
{
    int idx = blockIdx.x * 256 + threadIdx.x;
    float s = bp[idx & 511];
#pragma unroll 8
    for (int sp = 0; sp < 32; sp++) s += ws[sp * 65536 + idx];
    tp[idx] = s;
}

__global__ __launch_bounds__(512) void ln1_kernel(
    const float* __restrict__ attn, const float* __restrict__ tp,
    const float* __restrict__ g, const float* __restrict__ b, float* __restrict__ enh)
{
    int m = blockIdx.x, t = threadIdx.x;
    float x = attn[m * 512 + t] + tp[m * 512 + t];
    __shared__ float sS[16], sQ[16];
    __shared__ float mu_s, rs_s;
    float s = warp_sum(x), q = warp_sum(x * x);
    int wid = t >> 5, lane = t & 31;
    if (lane == 0) { sS[wid] = s; sQ[wid] = q; }
    __syncthreads();
    if (t == 0) {
        float S = 0, Q = 0;
        for (int i = 0; i < 16; i++) { S += sS[i]; Q += sQ[i]; }
        float mu = S * (1.f / 512.f);
        float var = Q * (1.f / 512.f) - mu * mu;
        mu_s = mu; rs_s = rsqrtf(var + EPS_);
    }
    __syncthreads();
    enh[m * 512 + t] = (x - mu_s) * rs_s * g[t] + b[t];
}

__global__ __launch_bounds__(256) void gap_kernel(
    const float* __restrict__ fa, float* __restrict__ gap)
{
    int m = blockIdx.x, t = threadIdx.x;
    int wid = t >> 5, lane = t & 31;
    for (int it = 0; it < 32; it++) {
        int c = wid * 32 + it;
        const float* p = fa + (size_t)m * 65536 + c * 256 + lane * 8;
        float4 a = *(const float4*)p;
        float4 b = *(const float4*)(p + 4);
        float s = a.x + a.y + a.z + a.w + b.x + b.y + b.z + b.w;
        s = warp_sum(s);
        if (lane == 0) gap[m * 256 + c] = s * (1.f / 256.f);
    }
}

__global__ __launch_bounds__(256) void dw_kernel(
    const float* __restrict__ fa, const float* __restrict__ kern, float* __restrict__ out)
{
    int c = blockIdx.x, m = blockIdx.y, t = threadIdx.x;
    __shared__ float tile[18][18];
    __shared__ float k9[9];
    for (int i = t; i < 324; i += 256) ((float*)tile)[i] = 0.f;
    __syncthreads();
    int h = t >> 4, w = t & 15;
    size_t base = (size_t)m * 65536 + c * 256;
    tile[h + 1][w + 1] = fa[base + t];
    if (t < 9) k9[t] = kern[m * 2304 + c * 9 + t];
    __syncthreads();
    float s = 0.f;
#pragma unroll
    for (int di = 0; di < 3; di++)
#pragma unroll
        for (int dj = 0; dj < 3; dj++)
            s += k9[di * 3 + dj] * tile[h + di][w + dj];
    out[base + t] = s;
}

__global__ __launch_bounds__(256) void gn_kernel(
    const float* __restrict__ X, const float* __restrict__ gg,
    const float* __restrict__ gb, float* __restrict__ O)
{
    int g = blockIdx.x, m = blockIdx.y, t = threadIdx.x;
    size_t base = (size_t)m * 65536 + g * 2048;
    float4 v0 = *(const float4*)&X[base + t * 8];
    float4 v1 = *(const float4*)&X[base + t * 8 + 4];
    float s = v0.x + v0.y + v0.z + v0.w + v1.x + v1.y + v1.z + v1.w;
    float q = v0.x * v0.x + v0.y * v0.y + v0.z * v0.z + v0.w * v0.w +
              v1.x * v1.x + v1.y * v1.y + v1.z * v1.z + v1.w * v1.w;
    __shared__ float sS[8], sQ[8];
    __shared__ float mu_s, rs_s;
    s = warp_sum(s); q = warp_sum(q);
    int wid = t >> 5, lane = t & 31;
    if (lane == 0) { sS[wid] = s; sQ[wid] = q; }
    __syncthreads();
    if (t == 0) {
        float S = 0, Q = 0;
        for (int i = 0; i < 8; i++) { S += sS[i]; Q += sQ[i]; }
        float mu = S * (1.f / 2048.f);
        float var = Q * (1.f / 2048.f) - mu * mu;
        mu_s = mu; rs_s = rsqrtf(var + EPS_);
    }
    __syncthreads();
    float vals[8] = {v0.x, v0.y, v0.z, v0.w, v1.x, v1.y, v1.z, v1.w};
#pragma unroll
    for (int j = 0; j < 8; j++) {
        int local = t * 8 + j;
        int c = g * 8 + (local >> 8);
        O[base + local] = (vals[j] - mu_s) * rs_s * gg[c] + gb[c];
    }
}

__global__ __launch_bounds__(256) void zstats_kernel(
    const float* __restrict__ z, float* __restrict__ mu_out, float* __restrict__ rs_out)
{
    int m = blockIdx.x, t = threadIdx.x;
    const float* row = z + (size_t)m * 65536;
    float s = 0.f, q = 0.f;
    for (int i = t * 4; i < 65536; i += 1024) {
        float4 v = *(const float4*)&row[i];
        s += v.x + v.y + v.z + v.w;
        q += v.x * v.x + v.y * v.y + v.z * v.z + v.w * v.w;
    }
    __shared__ float sS[8], sQ[8];
    s = warp_sum(s); q = warp_sum(q);
    int wid = t >> 5, lane = t & 31;
    if (lane == 0) { sS[wid] = s; sQ[wid] = q; }
    __syncthreads();
    if (t == 0) {
        float S = 0, Q = 0;
        for (int i = 0; i < 8; i++) { S += sS[i]; Q += sQ[i]; }
        float mu = S * (1.f / 65536.f);
        float var = Q * (1.f / 65536.f) - mu * mu;
        mu_out[m] = mu;
        rs_out[m] = rsqrtf(var + EPS_);
    }
}

__global__ __launch_bounds__(256) void final_kernel(
    const float* __restrict__ z, const float* __restrict__ mu, const float* __restrict__ rs,
    const float* __restrict__ dg, const float* __restrict__ db, float* __restrict__ out)
{
    int i4 = blockIdx.x * 256 + threadIdx.x;
    int idx = i4 * 4;
    int m = idx >> 16, j = idx & 65535;
    float4 zv = *(const float4*)&z[idx];
    float4 gv = *(const float4*)&dg[j];
    float4 bv = *(const float4*)&db[j];
    float mm = mu[m], rr = rs[m];
    float4 o;
    o.x = (zv.x - mm) * rr * gv.x + bv.x;
    o.y = (zv.y - mm) * rr * gv.y + bv.y;
    o.z = (zv.z - mm) * rr * gv.z + bv.z;
    o.w = (zv.w - mm) * rr * gv.w + bv.w;
    *(float4*)&out[idx] = o;
}

// ===========================================================================
extern "C" void kernel_launch(void* const* d_in, const int* in_sizes, int n_in,
                              void* d_out, int out_size)
{
    const float* feat = (const float*)d_in[0];
    const float* Wp   = (const float*)d_in[1];
    const float* bp   = (const float*)d_in[2];
    const float* Wu   = (const float*)d_in[3];
    const float* bu   = (const float*)d_in[4];
    // d_in[5..8] = Wq,bq,Wk,bk -> dead (softmax over size-1 axis == 1)
    const float* Wv   = (const float*)d_in[9];
    const float* bv   = (const float*)d_in[10];
    const float* Wo   = (const float*)d_in[11];
    const float* bo   = (const float*)d_in[12];
    const float* ln1g = (const float*)d_in[13];
    const float* ln1b = (const float*)d_in[14];
    const float* Wk1  = (const float*)d_in[15];
    const float* bk1  = (const float*)d_in[16];
    const float* Wk2  = (const float*)d_in[17];
    const float* bk2  = (const float*)d_in[18];
    const float* Wpc  = (const float*)d_in[19];
    const float* bpc  = (const float*)d_in[20];
    const float* gng  = (const float*)d_in[21];
    const float* gnb  = (const float*)d_in[22];
    const float* Wf1  = (const float*)d_in[23];
    const float* bf1  = (const float*)d_in[24];
    const float* Wf2  = (const float*)d_in[25];
    const float* bf2  = (const float*)d_in[26];
    const float* dng  = (const float*)d_in[27];
    const float* dnb  = (const float*)d_in[28];
    float* out = (float*)d_out;

    void* sp_ = nullptr;
    cudaGetSymbolAddress(&sp_, g_scratch);
    float* s = (float*)sp_;
    float* ws   = s;
    float* tp   = ws + 2097152;
    float* vv   = tp + 65536;
    float* attn = vv + 65536;
    float* enh  = attn + 65536;
    float* fa   = enh + 65536;
    float* b1   = fa + 8388608;
    float* b2   = b1 + 8388608;
    float* gapb = b2 + 8388608;
    float* hid  = gapb + 32768;
    float* kern = hid + 32768;
    float* muv  = kern + 294912;
    float* rsv  = muv + 128;

    // 1) tp = tokens @ Wp.T + bp   (tensor split-K=32 -> deterministic reduce)
    mg_kernel<0, 0, 0><<<dim3(8, 1, 32), 256>>>(feat, Wp, nullptr, nullptr, ws, 65536, 2048, 512, 65536);
    g1reduce_kernel<<<256, 256>>>(ws, bp, tp);
    // 2) vv = v_next @ Wv.T + bv ; attn = vv @ Wo.T + bo
    mg_kernel<1, 0, 1><<<dim3(8, 1, 1), 256>>>(tp, Wv, bv, nullptr, vv, 512, 512, 512, 512);
    mg_kernel<0, 0, 1><<<dim3(8, 1, 1), 256>>>(vv, Wo, bo, nullptr, attn, 512, 512, 512, 512);
    // 3) enh = LN(attn + tp)
    ln1_kernel<<<128, 512>>>(attn, tp, ln1g, ln1b, enh);
    // 4) feat_attn = enh @ Wu.T + bu
    mg_kernel<0, 0, 1><<<dim3(1024, 1, 1), 256>>>(enh, Wu, bu, nullptr, fa, 512, 512, 65536, 512);
    // 5) gap -> hid -> kern
    gap_kernel<<<128, 256>>>(fa, gapb);
    mg_kernel<0, 0, 2><<<dim3(4, 1, 1), 256>>>(gapb, Wk1, bk1, nullptr, hid, 256, 256, 256, 256);
    mg_kernel<0, 0, 1><<<dim3(36, 1, 1), 256>>>(hid, Wk2, bk2, nullptr, kern, 256, 256, 2304, 256);
    // 6) depthwise 3x3
    dw_kernel<<<dim3(256, 128), 256>>>(fa, kern, b1);
    // 7) pointwise Wpc + bpc, then GroupNorm
    mg_kernel<0, 1, 1><<<dim3(512, 2, 1), 256>>>(Wpc, b1, bpc, nullptr, b2, 256, 256, 0, 256);
    gn_kernel<<<dim3(32, 128), 256>>>(b2, gng, gnb, b1);
    // 8) y = relu(conv Wf1); y = conv Wf2 + feat_attn
    mg_kernel<0, 1, 2><<<dim3(512, 2, 1), 256>>>(Wf1, b1, bf1, nullptr, b2, 256, 256, 0, 256);
    mg_kernel<0, 1, 3><<<dim3(512, 2, 1), 256>>>(Wf2, b2, bf2, fa, b1, 256, 256, 0, 256);
    // 9) per-sample LayerNorm + affine
    zstats_kernel<<<128, 256>>>(b1, muv, rsv);
    final_kernel<<<8192, 256>>>(b1, muv, rsv, dng, dnb, out);
}

// round 4
// speedup vs baseline: 2.3173x; 1.1039x over previous
#include <cuda_runtime.h>
#include <cuda_bf16.h>
#include <cstdint>

#define EPS_ 1e-5f

// ---------------- scratch (single __device__ array) ----------------
__device__ float g_scratch[27885824];

__device__ __forceinline__ float warp_sum(float v) {
#pragma unroll
    for (int o = 16; o; o >>= 1) v += __shfl_down_sync(0xffffffffu, v, o);
    return v;
}

// split fp32 -> (hi bf16, lo bf16) pairs packed as bf16x2 words
__device__ __forceinline__ void cvt_split(float a, float b, uint32_t& hi, uint32_t& lo) {
    __nv_bfloat162 h = __floats2bfloat162_rn(a, b);
    float2 hf = __bfloat1622float2(h);
    __nv_bfloat162 l = __floats2bfloat162_rn(a - hf.x, b - hf.y);
    hi = *reinterpret_cast<uint32_t*>(&h);
    lo = *reinterpret_cast<uint32_t*>(&l);
}

__device__ __forceinline__ void mma16816(float* c, const uint32_t* a, const uint32_t* b) {
    asm volatile(
        "mma.sync.aligned.m16n8k16.row.col.f32.bf16.bf16.f32 "
        "{%0,%1,%2,%3}, {%4,%5,%6,%7}, {%8,%9}, {%0,%1,%2,%3};"
        : "+f"(c[0]), "+f"(c[1]), "+f"(c[2]), "+f"(c[3])
        : "r"(a[0]), "r"(a[1]), "r"(a[2]), "r"(a[3]), "r"(b[0]), "r"(b[1]));
}

// ===========================================================================
// mma.sync GEMM with register-prefetch pipelining.
// C[m,n] = act( sum_k A[m,k]*B[n,k] (+bias) (+res) )
// Block: 256 thr (8 warps), tile M=128 (blockIdx.y), N=64 (blockIdx.x),
// split-K = blockIdx.z (chunk length kLen). K-chunk 32 (bf16x3 split MMAs).
// SHIFT: remap A rows within frame-blocks of 32 (v_next).
// BCONV=1: B = X[n,c,p] gather (1x1 conv); column block = 64 px of one sample.
// EPI: 0=partial (split-K, no bias), 1=bias, 2=bias+relu, 3=bias+residual.
// ===========================================================================
#define SA 20  // smem row stride in 32-bit words (40 bf16)
template <int SHIFT, int BCONV, int EPI>
__global__ __launch_bounds__(256) void mg_kernel(
    const float* __restrict__ A, const float* __restrict__ Bm,
    const float* __restrict__ bias, const float* __restrict__ res,
    float* __restrict__ C, int K, int kLen, int Ntot, int Astride)
{
    __shared__ uint32_t AsH[128 * SA], AsL[128 * SA], BsH[64 * SA], BsL[64 * SA];
    const int t = threadIdx.x, w = t >> 5, lid = t & 31;
    const int wm = (w >> 1) * 32, wn = (w & 1) * 32;
    const int t4 = lid & 3, grp = lid >> 2;
    const int n0 = blockIdx.x * 64;
    const int m0 = blockIdx.y * 128;
    const int sp = blockIdx.z;
    const int k0base = sp * kLen;
    const int nn = n0 >> 8, p0 = n0 & 255;  // BCONV decode

    float acc[2][4][4];
#pragma unroll
    for (int i = 0; i < 2; i++)
#pragma unroll
        for (int j = 0; j < 4; j++)
#pragma unroll
            for (int q = 0; q < 4; q++) acc[i][j][q] = 0.f;

    // A-load mapping: row = t>>1, 16 consecutive cols at (t&1)*16
    int am = m0 + (t >> 1);
    if (SHIFT) { int bb = am >> 5, ii = (am & 31) + 1; if (ii > 31) ii = 31; am = (bb << 5) + ii; }
    const float* Aptr = A + (size_t)am * Astride + k0base + (t & 1) * 16;
    const int awb = (t >> 1) * SA + (t & 1) * 8;
    // B-load mapping
    const int bj = BCONV ? (t & 63) : (t >> 2);
    const int bcb = BCONV ? 0 : (t & 3) * 8;
    const int bcg = BCONV ? (t >> 6) : 0;
    const float* Bptr = BCONV
        ? Bm + (size_t)nn * 65536 + (size_t)(bcg * 8) * 256 + p0 + bj
        : Bm + (size_t)bj * K + k0base + bcb + (BCONV ? 0 : 0);
    if (!BCONV) Bptr = Bm + (size_t)(n0 + bj) * K + k0base + bcb;
    const int bwb = BCONV ? (bj * SA + bcg * 4) : (bj * SA + bcb / 2);

    const int nchunks = kLen >> 5;
    float apf[16], bpf[8];
    // ---- prefetch chunk 0 ----
    {
        const float* p = Aptr;
#pragma unroll
        for (int i = 0; i < 16; i += 4) {
            float4 v = *(const float4*)(p + i);
            apf[i] = v.x; apf[i + 1] = v.y; apf[i + 2] = v.z; apf[i + 3] = v.w;
        }
        if (!BCONV) {
#pragma unroll
            for (int i = 0; i < 8; i += 4) {
                float4 v = *(const float4*)(Bptr + i);
                bpf[i] = v.x; bpf[i + 1] = v.y; bpf[i + 2] = v.z; bpf[i + 3] = v.w;
            }
        } else {
#pragma unroll
            for (int i = 0; i < 8; i++) bpf[i] = Bptr[i * 256];
        }
    }

    for (int ch = 0; ch < nchunks; ch++) {
        __syncthreads();
        // ---- store prefetched chunk to smem (cvt to bf16 hi/lo) ----
#pragma unroll
        for (int i = 0; i < 16; i += 4) {
            uint32_t h0, l0, h1, l1;
            cvt_split(apf[i], apf[i + 1], h0, l0);
            cvt_split(apf[i + 2], apf[i + 3], h1, l1);
            AsH[awb + i / 2] = h0; AsH[awb + i / 2 + 1] = h1;
            AsL[awb + i / 2] = l0; AsL[awb + i / 2 + 1] = l1;
        }
#pragma unroll
        for (int i = 0; i < 8; i += 2) {
            uint32_t h, l;
            cvt_split(bpf[i], bpf[i + 1], h, l);
            BsH[bwb + i / 2] = h;
            BsL[bwb + i / 2] = l;
        }
        // ---- issue loads for next chunk (overlap with MMAs below) ----
        if (ch + 1 < nchunks) {
            const int kc = (ch + 1) << 5;
            const float* p = Aptr + kc;
#pragma unroll
            for (int i = 0; i < 16; i += 4) {
                float4 v = *(const float4*)(p + i);
                apf[i] = v.x; apf[i + 1] = v.y; apf[i + 2] = v.z; apf[i + 3] = v.w;
            }
            if (!BCONV) {
                const float* q = Bptr + kc;
#pragma unroll
                for (int i = 0; i < 8; i += 4) {
                    float4 v = *(const float4*)(q + i);
                    bpf[i] = v.x; bpf[i + 1] = v.y; bpf[i + 2] = v.z; bpf[i + 3] = v.w;
                }
            } else {
                const float* q = Bptr + (size_t)kc * 256;
#pragma unroll
                for (int i = 0; i < 8; i++) bpf[i] = q[i * 256];
            }
        }
        __syncthreads();
        // ---- compute: 2 k16 steps, 3 split passes each ----
#pragma unroll
        for (int ks = 0; ks < 2; ks++) {
            uint32_t ah[2][4], al[2][4], bh[4][2], bl[4][2];
#pragma unroll
            for (int mi = 0; mi < 2; mi++) {
                const int rb = (wm + mi * 16 + grp) * SA + ks * 8 + t4;
                ah[mi][0] = AsH[rb];       ah[mi][1] = AsH[rb + 8 * SA];
                ah[mi][2] = AsH[rb + 4];   ah[mi][3] = AsH[rb + 8 * SA + 4];
            }
#pragma unroll
            for (int ni = 0; ni < 4; ni++) {
                const int nb = (wn + ni * 8 + grp) * SA + ks * 8 + t4;
                bh[ni][0] = BsH[nb]; bh[ni][1] = BsH[nb + 4];
            }
#pragma unroll
            for (int mi = 0; mi < 2; mi++)
#pragma unroll
                for (int ni = 0; ni < 4; ni++) mma16816(acc[mi][ni], ah[mi], bh[ni]);
#pragma unroll
            for (int ni = 0; ni < 4; ni++) {
                const int nb = (wn + ni * 8 + grp) * SA + ks * 8 + t4;
                bl[ni][0] = BsL[nb]; bl[ni][1] = BsL[nb + 4];
            }
#pragma unroll
            for (int mi = 0; mi < 2; mi++)
#pragma unroll
                for (int ni = 0; ni < 4; ni++) mma16816(acc[mi][ni], ah[mi], bl[ni]);
#pragma unroll
            for (int mi = 0; mi < 2; mi++) {
                const int rb = (wm + mi * 16 + grp) * SA + ks * 8 + t4;
                al[mi][0] = AsL[rb];       al[mi][1] = AsL[rb + 8 * SA];
                al[mi][2] = AsL[rb + 4];   al[mi][3] = AsL[rb + 8 * SA + 4];
            }
#pragma unroll
            for (int mi = 0; mi < 2; mi++)
#pragma unroll
                for (int ni = 0; ni < 4; ni++) mma16816(acc[mi][ni], al[mi], bh[ni]);
        }
    }

    // ---- epilogue ----
#pragma unroll
    for (int mi = 0; mi < 2; mi++) {
        const int r0 = m0 + wm + mi * 16 + grp;
        const int r1 = r0 + 8;
        if (EPI == 0) {
            float* C0 = C + ((size_t)sp * 128 + r0) * Ntot + n0;
            float* C1 = C + ((size_t)sp * 128 + r1) * Ntot + n0;
#pragma unroll
            for (int ni = 0; ni < 4; ni++) {
                const int cw = wn + ni * 8 + 2 * t4;
                *(float2*)(C0 + cw) = make_float2(acc[mi][ni][0], acc[mi][ni][1]);
                *(float2*)(C1 + cw) = make_float2(acc[mi][ni][2], acc[mi][ni][3]);
            }
        } else if (!BCONV) {
            float* C0 = C + (size_t)r0 * Ntot;
            float* C1 = C + (size_t)r1 * Ntot;
#pragma unroll
            for (int ni = 0; ni < 4; ni++) {
                const int col = n0 + wn + ni * 8 + 2 * t4;
                float b0 = bias[col], b1 = bias[col + 1];
                float2 o0 = make_float2(acc[mi][ni][0] + b0, acc[mi][ni][1] + b1);
                float2 o1 = make_float2(acc[mi][ni][2] + b0, acc[mi][ni][3] + b1);
                if (EPI == 2) {
                    o0.x = fmaxf(o0.x, 0.f); o0.y = fmaxf(o0.y, 0.f);
                    o1.x = fmaxf(o1.x, 0.f); o1.y = fmaxf(o1.y, 0.f);
                }
                *(float2*)(C0 + col) = o0;
                *(float2*)(C1 + col) = o1;
            }
        } else {
            const float bm0 = bias[r0], bm1 = bias[r1];
            float* P0 = C + (size_t)nn * 65536 + (size_t)r0 * 256 + p0;
            float* P1 = C + (size_t)nn * 65536 + (size_t)r1 * 256 + p0;
            const float* R0 = (EPI == 3) ? res + (size_t)nn * 65536 + (size_t)r0 * 256 + p0 : nullptr;
            const float* R1 = (EPI == 3) ? res + (size_t)nn * 65536 + (size_t)r1 * 256 + p0 : nullptr;
#pragma unroll
            for (int ni = 0; ni < 4; ni++) {
                const int cw = wn + ni * 8 + 2 * t4;
                float2 o0 = make_float2(acc[mi][ni][0] + bm0, acc[mi][ni][1] + bm0);
                float2 o1 = make_float2(acc[mi][ni][2] + bm1, acc[mi][ni][3] + bm1);
                if (EPI == 2) {
                    o0.x = fmaxf(o0.x, 0.f); o0.y = fmaxf(o0.y, 0.f);
                    o1.x = fmaxf(o1.x, 0.f); o1.y = fmaxf(o1.y, 0.f);
                }
                if (EPI == 3) {
                    float2 q0 = *(const float2*)(R0 + cw);
                    float2 q1 = *(const float2*)(R1 + cw);
                    o0.x += q0.x; o0.y += q0.y; o1.x += q1.x; o1.y += q1.y;
                }
                *(float2*)(P0 + cw) = o0;
                *(float2*)(P1 + cw) = o1;
            }
        }
    }
}

// ===================== split-K reduce (+bias, optional relu) =====================
// out[idx] = act( bias[idx & (Ntot-1)] + sum_sp ws[sp*Nel + idx] ), Ntot pow2
template <int RELU>
__global__ __launch_bounds__(256) void spreduce_kernel(
    const float* __restrict__ ws, const float* __restrict__ bias,
    float* __restrict__ out, int nsp, int Nel, int NtotMask)
{
    int idx = blockIdx.x * 256 + threadIdx.x;
    if (idx >= Nel) return;
    float s = bias[idx & NtotMask];
    for (int sp = 0; sp < nsp; sp++) s += ws[(size_t)sp * Nel + idx];
    if (RELU) s = fmaxf(s, 0.f);
    out[idx] = s;
}

// ===================== SIMT kernels (mem-bound) =====================
__global__ __launch_bounds__(512) void ln1_kernel(
    const float* __restrict__ attn, const float* __restrict__ tp,
    const float* __restrict__ g, const float* __restrict__ b, float* __restrict__ enh)
{
    int m = blockIdx.x, t = threadIdx.x;
    float x = attn[m * 512 + t] + tp[m * 512 + t];
    __shared__ float sS[16], sQ[16];
    __shared__ float mu_s, rs_s;
    float s = warp_sum(x), q = warp_sum(x * x);
    int wid = t >> 5, lane = t & 31;
    if (lane == 0) { sS[wid] = s; sQ[wid] = q; }
    __syncthreads();
    if (t == 0) {
        float S = 0, Q = 0;
        for (int i = 0; i < 16; i++) { S += sS[i]; Q += sQ[i]; }
        float mu = S * (1.f / 512.f);
        float var = Q * (1.f / 512.f) - mu * mu;
        mu_s = mu; rs_s = rsqrtf(var + EPS_);
    }
    __syncthreads();
    enh[m * 512 + t] = (x - mu_s) * rs_s * g[t] + b[t];
}

__global__ __launch_bounds__(256) void gap_kernel(
    const float* __restrict__ fa, float* __restrict__ gap)
{
    int m = blockIdx.x, t = threadIdx.x;
    int wid = t >> 5, lane = t & 31;
    for (int it = 0; it < 32; it++) {
        int c = wid * 32 + it;
        const float* p = fa + (size_t)m * 65536 + c * 256 + lane * 8;
        float4 a = *(const float4*)p;
        float4 b = *(const float4*)(p + 4);
        float s = a.x + a.y + a.z + a.w + b.x + b.y + b.z + b.w;
        s = warp_sum(s);
        if (lane == 0) gap[m * 256 + c] = s * (1.f / 256.f);
    }
}

__global__ __launch_bounds__(256) void dw_kernel(
    const float* __restrict__ fa, const float* __restrict__ kern, float* __restrict__ out)
{
    int c = blockIdx.x, m = blockIdx.y, t = threadIdx.x;
    __shared__ float tile[18][18];
    __shared__ float k9[9];
    for (int i = t; i < 324; i += 256) ((float*)tile)[i] = 0.f;
    __syncthreads();
    int h = t >> 4, w = t & 15;
    size_t base = (size_t)m * 65536 + c * 256;
    tile[h + 1][w + 1] = fa[base + t];
    if (t < 9) k9[t] = kern[m * 2304 + c * 9 + t];
    __syncthreads();
    float s = 0.f;
#pragma unroll
    for (int di = 0; di < 3; di++)
#pragma unroll
        for (int dj = 0; dj < 3; dj++)
            s += k9[di * 3 + dj] * tile[h + di][w + dj];
    out[base + t] = s;
}

__global__ __launch_bounds__(256) void gn_kernel(
    const float* __restrict__ X, const float* __restrict__ gg,
    const float* __restrict__ gb, float* __restrict__ O)
{
    int g = blockIdx.x, m = blockIdx.y, t = threadIdx.x;
    size_t base = (size_t)m * 65536 + g * 2048;
    float4 v0 = *(const float4*)&X[base + t * 8];
    float4 v1 = *(const float4*)&X[base + t * 8 + 4];
    float s = v0.x + v0.y + v0.z + v0.w + v1.x + v1.y + v1.z + v1.w;
    float q = v0.x * v0.x + v0.y * v0.y + v0.z * v0.z + v0.w * v0.w +
              v1.x * v1.x + v1.y * v1.y + v1.z * v1.z + v1.w * v1.w;
    __shared__ float sS[8], sQ[8];
    __shared__ float mu_s, rs_s;
    s = warp_sum(s); q = warp_sum(q);
    int wid = t >> 5, lane = t & 31;
    if (lane == 0) { sS[wid] = s; sQ[wid] = q; }
    __syncthreads();
    if (t == 0) {
        float S = 0, Q = 0;
        for (int i = 0; i < 8; i++) { S += sS[i]; Q += sQ[i]; }
        float mu = S * (1.f / 2048.f);
        float var = Q * (1.f / 2048.f) - mu * mu;
        mu_s = mu; rs_s = rsqrtf(var + EPS_);
    }
    __syncthreads();
    float vals[8] = {v0.x, v0.y, v0.z, v0.w, v1.x, v1.y, v1.z, v1.w};
#pragma unroll
    for (int j = 0; j < 8; j++) {
        int local = t * 8 + j;
        int c = g * 8 + (local >> 8);
        O[base + local] = (vals[j] - mu_s) * rs_s * gg[c] + gb[c];
    }
}

__global__ __launch_bounds__(256) void zstats_kernel(
    const float* __restrict__ z, float* __restrict__ mu_out, float* __restrict__ rs_out)
{
    int m = blockIdx.x, t = threadIdx.x;
    const float* row = z + (size_t)m * 65536;
    float s = 0.f, q = 0.f;
    for (int i = t * 4; i < 65536; i += 1024) {
        float4 v = *(const float4*)&row[i];
        s += v.x + v.y + v.z + v.w;
        q += v.x * v.x + v.y * v.y + v.z * v.z + v.w * v.w;
    }
    __shared__ float sS[8], sQ[8];
    s = warp_sum(s); q = warp_sum(q);
    int wid = t >> 5, lane = t & 31;
    if (lane == 0) { sS[wid] = s; sQ[wid] = q; }
    __syncthreads();
    if (t == 0) {
        float S = 0, Q = 0;
        for (int i = 0; i < 8; i++) { S += sS[i]; Q += sQ[i]; }
        float mu = S * (1.f / 65536.f);
        float var = Q * (1.f / 65536.f) - mu * mu;
        mu_out[m] = mu;
        rs_out[m] = rsqrtf(var + EPS_);
    }
}

__global__ __launch_bounds__(256) void final_kernel(
    const float* __restrict__ z, const float* __restrict__ mu, const float* __restrict__ rs,
    const float* __restrict__ dg, const float* __restrict__ db, float* __restrict__ out)
{
    int i4 = blockIdx.x * 256 + threadIdx.x;
    int idx = i4 * 4;
    int m = idx >> 16, j = idx & 65535;
    float4 zv = *(const float4*)&z[idx];
    float4 gv = *(const float4*)&dg[j];
    float4 bv = *(const float4*)&db[j];
    float mm = mu[m], rr = rs[m];
    float4 o;
    o.x = (zv.x - mm) * rr * gv.x + bv.x;
    o.y = (zv.y - mm) * rr * gv.y + bv.y;
    o.z = (zv.z - mm) * rr * gv.z + bv.z;
    o.w = (zv.w - mm) * rr * gv.w + bv.w;
    *(float4*)&out[idx] = o;
}

// ===========================================================================
extern "C" void kernel_launch(void* const* d_in, const int* in_sizes, int n_in,
                              void* d_out, int out_size)
{
    const float* feat = (const float*)d_in[0];
    const float* Wp   = (const float*)d_in[1];
    const float* bp   = (const float*)d_in[2];
    const float* Wu   = (const float*)d_in[3];
    const float* bu   = (const float*)d_in[4];
    // d_in[5..8] = Wq,bq,Wk,bk -> dead (softmax over size-1 axis == 1)
    const float* Wv   = (const float*)d_in[9];
    const float* bv   = (const float*)d_in[10];
    const float* Wo   = (const float*)d_in[11];
    const float* bo   = (const float*)d_in[12];
    const float* ln1g = (const float*)d_in[13];
    const float* ln1b = (const float*)d_in[14];
    const float* Wk1  = (const float*)d_in[15];
    const float* bk1  = (const float*)d_in[16];
    const float* Wk2  = (const float*)d_in[17];
    const float* bk2  = (const float*)d_in[18];
    const float* Wpc  = (const float*)d_in[19];
    const float* bpc  = (const float*)d_in[20];
    const float* gng  = (const float*)d_in[21];
    const float* gnb  = (const float*)d_in[22];
    const float* Wf1  = (const float*)d_in[23];
    const float* bf1  = (const float*)d_in[24];
    const float* Wf2  = (const float*)d_in[25];
    const float* bf2  = (const float*)d_in[26];
    const float* dng  = (const float*)d_in[27];
    const float* dnb  = (const float*)d_in[28];
    float* out = (float*)d_out;

    void* sp_ = nullptr;
    cudaGetSymbolAddress(&sp_, g_scratch);
    float* s = (float*)sp_;
    float* ws   = s;
    float* tp   = ws + 2097152;
    float* vv   = tp + 65536;
    float* attn = vv + 65536;
    float* enh  = attn + 65536;
    float* fa   = enh + 65536;
    float* b1   = fa + 8388608;
    float* b2   = b1 + 8388608;
    float* gapb = b2 + 8388608;
    float* hid  = gapb + 32768;
    float* kern = hid + 32768;
    float* muv  = kern + 294912;
    float* rsv  = muv + 128;

    // 1) tp = tokens @ Wp.T + bp   (split-K=32 -> deterministic reduce)
    mg_kernel<0, 0, 0><<<dim3(8, 1, 32), 256>>>(feat, Wp, nullptr, nullptr, ws, 65536, 2048, 512, 65536);
    spreduce_kernel<0><<<256, 256>>>(ws, bp, tp, 32, 65536, 511);
    // 2) vv = v_next @ Wv.T + bv ; attn = vv @ Wo.T + bo  (split-K=4 each)
    mg_kernel<1, 0, 0><<<dim3(8, 1, 4), 256>>>(tp, Wv, nullptr, nullptr, ws, 512, 128, 512, 512);
    spreduce_kernel<0><<<256, 256>>>(ws, bv, vv, 4, 65536, 511);
    mg_kernel<0, 0, 0><<<dim3(8, 1, 4), 256>>>(vv, Wo, nullptr, nullptr, ws, 512, 128, 512, 512);
    spreduce_kernel<0><<<256, 256>>>(ws, bo, attn, 4, 65536, 511);
    // 3) enh = LN(attn + tp)
    ln1_kernel<<<128, 512>>>(attn, tp, ln1g, ln1b, enh);
    // 4) feat_attn = enh @ Wu.T + bu
    mg_kernel<0, 0, 1><<<dim3(1024, 1, 1), 256>>>(enh, Wu, bu, nullptr, fa, 512, 512, 65536, 512);
    // 5) gap -> hid -> kern
    gap_kernel<<<128, 256>>>(fa, gapb);
    mg_kernel<0, 0, 0><<<dim3(4, 1, 2), 256>>>(gapb, Wk1, nullptr, nullptr, ws, 256, 128, 256, 256);
    spreduce_kernel<1><<<128, 256>>>(ws, bk1, hid, 2, 32768, 255);
    mg_kernel<0, 0, 1><<<dim3(36, 1, 1), 256>>>(hid, Wk2, bk2, nullptr, kern, 256, 256, 2304, 256);
    // 6) depthwise 3x3
    dw_kernel<<<dim3(256, 128), 256>>>(fa, kern, b1);
    // 7) pointwise Wpc + bpc, then GroupNorm
    mg_kernel<0, 1, 1><<<dim3(512, 2, 1), 256>>>(Wpc, b1, bpc, nullptr, b2, 256, 256, 0, 256);
    gn_kernel<<<dim3(32, 128), 256>>>(b2, gng, gnb, b1);
    // 8) y = relu(conv Wf1); y = conv Wf2 + feat_attn
    mg_kernel<0, 1, 2><<<dim3(512, 2, 1), 256>>>(Wf1, b1, bf1, nullptr, b2, 256, 256, 0, 256);
    mg_kernel<0, 1, 3><<<dim3(512, 2, 1), 256>>>(Wf2, b2, bf2, fa, b1, 256, 256, 0, 256);
    // 9) per-sample LayerNorm + affine
    zstats_kernel<<<128, 256>>>(b1, muv, rsv);
    final_kernel<<<8192, 256>>>(b1, muv, rsv, dng, dnb, out);
}